// round 4
// baseline (speedup 1.0000x reference)
#include <cuda_runtime.h>
#include <math.h>

// ---------------- problem constants ----------------
#define T_TOK 2048      // B*S
#define HDIM  1024
#define SSEQ  1024
#define BB    2
#define NHQ   16
#define NKVH  4
#define HDH   64
#define NEXP  64
#define TOPK  8
#define IE    512
#define IS    1408

// ---------------- scratch arena (static, no allocs) ----------------
// floats
static const size_t OFF_X    = 0;          // [T,1024]
static const size_t OFF_QKV  = 2097152;    // [T,1536]  q|k|v packed
static const size_t OFF_ATTN = 5242880;    // [T,1024]
static const size_t OFF_H    = 7340032;    // [T,1024]
static const size_t OFF_Y    = 9437184;    // [T,1024]
static const size_t OFF_MOE  = 11534336;   // [T,1024]
static const size_t OFF_SINT = 13631488;   // [T,1408]
static const size_t OFF_LOG  = 16515072;   // [T,64]
static const size_t OFF_G    = 16646144;   // [T]
static const size_t OFF_WTS  = 16648192;   // [E,2048]
static const size_t OFF_INT  = 16779264;   // [E*2048, 512]
__device__ float g_arena[83888128];
__device__ int   g_iarena[131136];         // toks [E,2048] then counts[64]

// ---------------- helpers ----------------
__device__ __forceinline__ float block_sum_256(float v) {
    __shared__ float red[8];
    #pragma unroll
    for (int o = 16; o; o >>= 1) v += __shfl_xor_sync(0xffffffffu, v, o);
    if ((threadIdx.x & 31) == 0) red[threadIdx.x >> 5] = v;
    __syncthreads();
    if (threadIdx.x == 0) {
        float s = 0.f;
        #pragma unroll
        for (int i = 0; i < 8; i++) s += red[i];
        red[0] = s;
    }
    __syncthreads();
    return red[0];
}

// ---------------- elementwise / norm kernels ----------------
__global__ void zero_counts_kernel(int* counts) { counts[threadIdx.x] = 0; }

__global__ void rmsnorm_kernel(const float* __restrict__ x, const float* __restrict__ w,
                               float* __restrict__ out) {
    int t = blockIdx.x;
    const float* xr = x + (size_t)t * HDIM;
    float s = 0.f;
    for (int i = threadIdx.x; i < HDIM; i += 256) { float v = xr[i]; s += v * v; }
    s = block_sum_256(s);
    float inv = rsqrtf(s * (1.0f / HDIM) + 1e-6f);
    float* orow = out + (size_t)t * HDIM;
    for (int i = threadIdx.x; i < HDIM; i += 256) orow[i] = xr[i] * inv * w[i];
}

__global__ void sgate_kernel(const float* __restrict__ y, const float* __restrict__ shw,
                             float* __restrict__ g) {
    int t = blockIdx.x;
    const float* yr = y + (size_t)t * HDIM;
    float s = 0.f;
    for (int i = threadIdx.x; i < HDIM; i += 256) s += yr[i] * shw[i];
    s = block_sum_256(s);
    if (threadIdx.x == 0) g[t] = 1.0f / (1.0f + expf(-s));
}

__global__ void rope_kernel(float* __restrict__ qkv) {
    __shared__ float cs[32], sn[32];
    int t = blockIdx.x;
    int s = t & (SSEQ - 1);
    if (threadIdx.x < 32) {
        double inv = exp(-(double)threadIdx.x / 32.0 * log(1000000.0));
        double ang = (double)s * inv;
        cs[threadIdx.x] = (float)cos(ang);
        sn[threadIdx.x] = (float)sin(ang);
    }
    __syncthreads();
    float* base = qkv + (size_t)t * 1536;
    for (int w = threadIdx.x; w < 20 * 32; w += blockDim.x) {
        int hh = w >> 5, i = w & 31;
        float* p = base + (hh < 16 ? hh * 64 : 1024 + (hh - 16) * 64);
        float x1 = p[i], x2 = p[i + 32];
        float c = cs[i], s2 = sn[i];
        p[i]      = x1 * c - x2 * s2;
        p[i + 32] = x2 * c + x1 * s2;
    }
}

__global__ void add_kernel(const float* __restrict__ a, const float* __restrict__ b,
                           float* __restrict__ o, int n) {
    for (int i = blockIdx.x * blockDim.x + threadIdx.x; i < n; i += gridDim.x * blockDim.x)
        o[i] = a[i] + b[i];
}

// ---------------- generic NT SGEMM: C = res + scale*(A@B^T + bias) ----------------
// A [M,K] lda; B [N,K] ldb; tiles 128x64x16, 256 threads, 8x4 per thread.
__global__ void __launch_bounds__(256) gemm_nt_kernel(
    const float* __restrict__ A, int lda,
    const float* __restrict__ B, int ldb,
    const float* __restrict__ bias,
    const float* __restrict__ res, int ldres,
    const float* __restrict__ scale,
    float* __restrict__ C, int ldc,
    int M, int N, int K)
{
    __shared__ float As[16][128];
    __shared__ float Bs[16][64];
    const int mb = blockIdx.y * 128;
    const int nb = blockIdx.x * 64;
    const int tid = threadIdx.x;
    const int tm = (tid >> 4) * 8;
    const int tn = (tid & 15) * 4;
    float acc[8][4];
    #pragma unroll
    for (int i = 0; i < 8; i++)
        #pragma unroll
        for (int j = 0; j < 4; j++) acc[i][j] = 0.f;

    for (int kb = 0; kb < K; kb += 16) {
        #pragma unroll
        for (int i = 0; i < 2; i++) {
            int f4 = tid + i * 256;
            int m = f4 >> 2, k4 = (f4 & 3) << 2;
            float4 v = make_float4(0.f, 0.f, 0.f, 0.f);
            int gm = mb + m;
            if (gm < M) v = *(const float4*)(A + (size_t)gm * lda + kb + k4);
            As[k4][m] = v.x; As[k4 + 1][m] = v.y; As[k4 + 2][m] = v.z; As[k4 + 3][m] = v.w;
        }
        {
            int n = tid >> 2, k4 = (tid & 3) << 2;
            int gn = nb + n;
            float4 v = make_float4(0.f, 0.f, 0.f, 0.f);
            if (gn < N) v = *(const float4*)(B + (size_t)gn * ldb + kb + k4);
            Bs[k4][n] = v.x; Bs[k4 + 1][n] = v.y; Bs[k4 + 2][n] = v.z; Bs[k4 + 3][n] = v.w;
        }
        __syncthreads();
        #pragma unroll
        for (int k = 0; k < 16; k++) {
            float4 a0 = *(const float4*)&As[k][tm];
            float4 a1 = *(const float4*)&As[k][tm + 4];
            float4 b  = *(const float4*)&Bs[k][tn];
            float av[8] = {a0.x, a0.y, a0.z, a0.w, a1.x, a1.y, a1.z, a1.w};
            float bv[4] = {b.x, b.y, b.z, b.w};
            #pragma unroll
            for (int i = 0; i < 8; i++)
                #pragma unroll
                for (int j = 0; j < 4; j++) acc[i][j] += av[i] * bv[j];
        }
        __syncthreads();
    }
    #pragma unroll
    for (int i = 0; i < 8; i++) {
        int gm = mb + tm + i;
        if (gm >= M) break;
        float sc = scale ? scale[gm] : 1.f;
        #pragma unroll
        for (int j = 0; j < 4; j++) {
            int gn = nb + tn + j;
            float v = acc[i][j];
            if (bias) v += bias[gn];
            v *= sc;
            if (res) v += res[(size_t)gm * ldres + gn];
            C[(size_t)gm * ldc + gn] = v;
        }
    }
}

// ---------------- NT gate/up fused GEMM: C = silu(A@Bg^T) * (A@Bu^T) ----------------
// tiles 64x64x16, 256 threads, 4x4 per thread per matrix.
__global__ void __launch_bounds__(256) gemm_nt_gateup_kernel(
    const float* __restrict__ A, int lda,
    const float* __restrict__ Bg, const float* __restrict__ Bu, int ldb,
    float* __restrict__ C, int ldc, int M, int N, int K)
{
    __shared__ float As[16][64];
    __shared__ float Bsg[16][64];
    __shared__ float Bsu[16][64];
    const int mb = blockIdx.y * 64;
    const int nb = blockIdx.x * 64;
    const int tid = threadIdx.x;
    const int tm = (tid >> 4) * 4;
    const int tn = (tid & 15) * 4;
    float ag[4][4], au[4][4];
    #pragma unroll
    for (int i = 0; i < 4; i++)
        #pragma unroll
        for (int j = 0; j < 4; j++) { ag[i][j] = 0.f; au[i][j] = 0.f; }

    for (int kb = 0; kb < K; kb += 16) {
        {
            int m = tid >> 2, k4 = (tid & 3) << 2;
            int gm = mb + m;
            float4 v = make_float4(0.f, 0.f, 0.f, 0.f);
            if (gm < M) v = *(const float4*)(A + (size_t)gm * lda + kb + k4);
            As[k4][m] = v.x; As[k4 + 1][m] = v.y; As[k4 + 2][m] = v.z; As[k4 + 3][m] = v.w;
        }
        {
            int n = tid >> 2, k4 = (tid & 3) << 2;
            int gn = nb + n;
            float4 vg = make_float4(0.f, 0.f, 0.f, 0.f), vu = vg;
            if (gn < N) {
                vg = *(const float4*)(Bg + (size_t)gn * ldb + kb + k4);
                vu = *(const float4*)(Bu + (size_t)gn * ldb + kb + k4);
            }
            Bsg[k4][n] = vg.x; Bsg[k4 + 1][n] = vg.y; Bsg[k4 + 2][n] = vg.z; Bsg[k4 + 3][n] = vg.w;
            Bsu[k4][n] = vu.x; Bsu[k4 + 1][n] = vu.y; Bsu[k4 + 2][n] = vu.z; Bsu[k4 + 3][n] = vu.w;
        }
        __syncthreads();
        #pragma unroll
        for (int k = 0; k < 16; k++) {
            float4 a  = *(const float4*)&As[k][tm];
            float4 bg = *(const float4*)&Bsg[k][tn];
            float4 bu = *(const float4*)&Bsu[k][tn];
            float av[4] = {a.x, a.y, a.z, a.w};
            float gv[4] = {bg.x, bg.y, bg.z, bg.w};
            float uv[4] = {bu.x, bu.y, bu.z, bu.w};
            #pragma unroll
            for (int i = 0; i < 4; i++)
                #pragma unroll
                for (int j = 0; j < 4; j++) {
                    ag[i][j] += av[i] * gv[j];
                    au[i][j] += av[i] * uv[j];
                }
        }
        __syncthreads();
    }
    #pragma unroll
    for (int i = 0; i < 4; i++) {
        int gm = mb + tm + i;
        if (gm >= M) break;
        #pragma unroll
        for (int j = 0; j < 4; j++) {
            int gn = nb + tn + j;
            float gv = ag[i][j], uv = au[i][j];
            C[(size_t)gm * ldc + gn] = gv / (1.0f + expf(-gv)) * uv;
        }
    }
}

// ---------------- expert gate/up: gathered-A NN GEMM ----------------
// A rows = y[toks[e,slot]], Bg/Bu [K=H, N=IE] row-major (n contiguous), 64x64x16.
__global__ void __launch_bounds__(256) expert_gateup_kernel(
    const float* __restrict__ Y,
    const float* __restrict__ Wg, const float* __restrict__ Wu,
    const int* __restrict__ toks, const int* __restrict__ counts,
    float* __restrict__ inter)
{
    const int e = blockIdx.z;
    const int cnt = counts[e];
    const int mb = blockIdx.y * 64;
    if (mb >= cnt) return;
    const int nb = blockIdx.x * 64;
    const float* Bg = Wg + (size_t)e * HDIM * IE;
    const float* Bu = Wu + (size_t)e * HDIM * IE;
    const int* tk = toks + e * T_TOK;
    __shared__ float As[16][64];
    __shared__ float Bsg[16][64];
    __shared__ float Bsu[16][64];
    const int tid = threadIdx.x;
    const int tm = (tid >> 4) * 4;
    const int tn = (tid & 15) * 4;
    float ag[4][4], au[4][4];
    #pragma unroll
    for (int i = 0; i < 4; i++)
        #pragma unroll
        for (int j = 0; j < 4; j++) { ag[i][j] = 0.f; au[i][j] = 0.f; }

    for (int kb = 0; kb < HDIM; kb += 16) {
        {
            int m = tid >> 2, k4 = (tid & 3) << 2;
            int gm = mb + m;
            float4 v = make_float4(0.f, 0.f, 0.f, 0.f);
            if (gm < cnt) {
                int row = tk[gm];
                v = *(const float4*)(Y + (size_t)row * HDIM + kb + k4);
            }
            As[k4][m] = v.x; As[k4 + 1][m] = v.y; As[k4 + 2][m] = v.z; As[k4 + 3][m] = v.w;
        }
        {
            int kk = tid >> 4, n4 = (tid & 15) << 2;
            *(float4*)&Bsg[kk][n4] = *(const float4*)(Bg + (size_t)(kb + kk) * IE + nb + n4);
            *(float4*)&Bsu[kk][n4] = *(const float4*)(Bu + (size_t)(kb + kk) * IE + nb + n4);
        }
        __syncthreads();
        #pragma unroll
        for (int k = 0; k < 16; k++) {
            float4 a  = *(const float4*)&As[k][tm];
            float4 bg = *(const float4*)&Bsg[k][tn];
            float4 bu = *(const float4*)&Bsu[k][tn];
            float av[4] = {a.x, a.y, a.z, a.w};
            float gv[4] = {bg.x, bg.y, bg.z, bg.w};
            float uv[4] = {bu.x, bu.y, bu.z, bu.w};
            #pragma unroll
            for (int i = 0; i < 4; i++)
                #pragma unroll
                for (int j = 0; j < 4; j++) {
                    ag[i][j] += av[i] * gv[j];
                    au[i][j] += av[i] * uv[j];
                }
        }
        __syncthreads();
    }
    #pragma unroll
    for (int i = 0; i < 4; i++) {
        int gm = mb + tm + i;
        if (gm < cnt) {
            float* Cp = inter + ((size_t)e * T_TOK + gm) * IE + nb + tn;
            #pragma unroll
            for (int j = 0; j < 4; j++) {
                float gv = ag[i][j], uv = au[i][j];
                Cp[j] = gv / (1.0f + expf(-gv)) * uv;
            }
        }
    }
}

// ---------------- expert down: NN GEMM + weighted atomic scatter ----------------
__global__ void __launch_bounds__(256) expert_down_kernel(
    const float* __restrict__ inter, const float* __restrict__ Wd,
    const int* __restrict__ toks, const int* __restrict__ counts,
    const float* __restrict__ wts, float* __restrict__ moe)
{
    const int e = blockIdx.z;
    const int cnt = counts[e];
    const int mb = blockIdx.y * 128;
    if (mb >= cnt) return;
    const int nb = blockIdx.x * 64;
    const float* Aexp = inter + (size_t)e * T_TOK * IE;
    const float* B = Wd + (size_t)e * IE * HDIM;
    __shared__ float As[16][128];
    __shared__ float Bs[16][64];
    const int tid = threadIdx.x;
    const int tm = (tid >> 4) * 8;
    const int tn = (tid & 15) * 4;
    float acc[8][4];
    #pragma unroll
    for (int i = 0; i < 8; i++)
        #pragma unroll
        for (int j = 0; j < 4; j++) acc[i][j] = 0.f;

    for (int kb = 0; kb < IE; kb += 16) {
        #pragma unroll
        for (int i = 0; i < 2; i++) {
            int f4 = tid + i * 256;
            int m = f4 >> 2, k4 = (f4 & 3) << 2;
            float4 v = make_float4(0.f, 0.f, 0.f, 0.f);
            int gm = mb + m;
            if (gm < cnt) v = *(const float4*)(Aexp + (size_t)gm * IE + kb + k4);
            As[k4][m] = v.x; As[k4 + 1][m] = v.y; As[k4 + 2][m] = v.z; As[k4 + 3][m] = v.w;
        }
        {
            int kk = tid >> 4, n4 = (tid & 15) << 2;
            *(float4*)&Bs[kk][n4] = *(const float4*)(B + (size_t)(kb + kk) * HDIM + nb + n4);
        }
        __syncthreads();
        #pragma unroll
        for (int k = 0; k < 16; k++) {
            float4 a0 = *(const float4*)&As[k][tm];
            float4 a1 = *(const float4*)&As[k][tm + 4];
            float4 b  = *(const float4*)&Bs[k][tn];
            float av[8] = {a0.x, a0.y, a0.z, a0.w, a1.x, a1.y, a1.z, a1.w};
            float bv[4] = {b.x, b.y, b.z, b.w};
            #pragma unroll
            for (int i = 0; i < 8; i++)
                #pragma unroll
                for (int j = 0; j < 4; j++) acc[i][j] += av[i] * bv[j];
        }
        __syncthreads();
    }
    #pragma unroll
    for (int i = 0; i < 8; i++) {
        int gm = mb + tm + i;
        if (gm < cnt) {
            int t = toks[e * T_TOK + gm];
            float w = wts[e * T_TOK + gm];
            float* mp = moe + (size_t)t * HDIM + nb + tn;
            #pragma unroll
            for (int j = 0; j < 4; j++) atomicAdd(&mp[j], w * acc[i][j]);
        }
    }
}

// ---------------- router top-k ----------------
__global__ void router_kernel(const float* __restrict__ logits, int* __restrict__ counts,
                              int* __restrict__ toks, float* __restrict__ wts) {
    int t = blockIdx.x * blockDim.x + threadIdx.x;
    if (t >= T_TOK) return;
    float v[NEXP];
    float mx = -1e30f;
    for (int e = 0; e < NEXP; e++) { v[e] = logits[t * NEXP + e]; mx = fmaxf(mx, v[e]); }
    for (int e = 0; e < NEXP; e++) v[e] = expf(v[e] - mx);
    // top-8 on unnormalized exp values (softmax normalizer cancels in renorm)
    int idx[TOPK]; float w8[TOPK]; float tw = 0.f;
    for (int j = 0; j < TOPK; j++) {
        int am = 0; float bm = -1.f;
        for (int e = 0; e < NEXP; e++) if (v[e] > bm) { bm = v[e]; am = e; }
        idx[j] = am; w8[j] = bm; tw += bm; v[am] = -2.f;
    }
    for (int j = 0; j < TOPK; j++) {
        int e = idx[j];
        int p = atomicAdd(&counts[e], 1);
        toks[e * T_TOK + p] = t;
        wts[e * T_TOK + p] = w8[j] / tw;
    }
}

// ---------------- flash attention (causal, GQA 16q/4kv, HD=64) ----------------
__global__ void __launch_bounds__(256) attn_kernel(const float* __restrict__ qkv,
                                                   float* __restrict__ out) {
    const int qt = blockIdx.x, h = blockIdx.y, b = blockIdx.z;
    const int q0 = qt * 32;
    const int kvh = h >> 2;
    __shared__ float Qs[32][68];
    __shared__ float KVs[64][68];
    __shared__ float Ss[32][68];
    const int tid = threadIdx.x;
    const int r = tid >> 3;     // q row 0..31
    const int cth = tid & 7;    // col/dim lane 0..7
    for (int i = tid; i < 32 * 64; i += 256) {
        int rr = i >> 6, d = i & 63;
        Qs[rr][d] = qkv[(size_t)(b * SSEQ + q0 + rr) * 1536 + h * 64 + d];
    }
    float m = -1e30f, l = 0.f;
    float oa[8];
    #pragma unroll
    for (int i = 0; i < 8; i++) oa[i] = 0.f;
    const int qg = q0 + r;
    const int ntiles = q0 / 64 + 1;
    for (int tkv = 0; tkv < ntiles; tkv++) {
        const int kb = tkv * 64;
        for (int i = tid; i < 64 * 64; i += 256) {
            int rr = i >> 6, d = i & 63;
            KVs[rr][d] = qkv[(size_t)(b * SSEQ + kb + rr) * 1536 + 1024 + kvh * 64 + d];
        }
        __syncthreads();
        float sv[8];
        #pragma unroll
        for (int ci = 0; ci < 8; ci++) {
            int c = cth + ci * 8;
            float s = 0.f;
            #pragma unroll
            for (int d = 0; d < 64; d++) s += Qs[r][d] * KVs[c][d];
            sv[ci] = (kb + c <= qg) ? s * 0.125f : -1e30f;
        }
        float tmax = sv[0];
        #pragma unroll
        for (int ci = 1; ci < 8; ci++) tmax = fmaxf(tmax, sv[ci]);
        #pragma unroll
        for (int o = 4; o; o >>= 1) tmax = fmaxf(tmax, __shfl_xor_sync(0xffffffffu, tmax, o, 8));
        float newm = fmaxf(m, tmax);
        float corr = expf(m - newm);
        float ls = 0.f;
        #pragma unroll
        for (int ci = 0; ci < 8; ci++) {
            float p = expf(sv[ci] - newm);
            Ss[r][cth + ci * 8] = p;
            ls += p;
        }
        #pragma unroll
        for (int o = 4; o; o >>= 1) ls += __shfl_xor_sync(0xffffffffu, ls, o, 8);
        l = l * corr + ls;
        #pragma unroll
        for (int i = 0; i < 8; i++) oa[i] *= corr;
        m = newm;
        __syncthreads();
        for (int i = tid; i < 64 * 64; i += 256) {
            int rr = i >> 6, d = i & 63;
            KVs[rr][d] = qkv[(size_t)(b * SSEQ + kb + rr) * 1536 + 1280 + kvh * 64 + d];
        }
        __syncthreads();
        #pragma unroll 16
        for (int k = 0; k < 64; k++) {
            float p = Ss[r][k];
            #pragma unroll
            for (int i = 0; i < 8; i++) oa[i] += p * KVs[k][cth + i * 8];
        }
        __syncthreads();
    }
    float inv = 1.f / l;
    #pragma unroll
    for (int i = 0; i < 8; i++)
        out[(size_t)(b * SSEQ + q0 + r) * 1024 + h * 64 + cth + i * 8] = oa[i] * inv;
}

// ---------------- launch ----------------
extern "C" void kernel_launch(void* const* d_in, const int* in_sizes, int n_in,
                              void* d_out, int out_size) {
    const float* hid    = (const float*)d_in[0];
    const float* ln1    = (const float*)d_in[1];
    const float* ln2    = (const float*)d_in[2];
    const float* q_w    = (const float*)d_in[3];
    const float* q_b    = (const float*)d_in[4];
    const float* k_w    = (const float*)d_in[5];
    const float* k_b    = (const float*)d_in[6];
    const float* v_w    = (const float*)d_in[7];
    const float* v_b    = (const float*)d_in[8];
    const float* o_w    = (const float*)d_in[9];
    const float* gate_w = (const float*)d_in[10];
    const float* w_gate = (const float*)d_in[11];
    const float* w_up   = (const float*)d_in[12];
    const float* w_down = (const float*)d_in[13];
    const float* s_gate = (const float*)d_in[14];
    const float* s_up   = (const float*)d_in[15];
    const float* s_down = (const float*)d_in[16];
    const float* shg    = (const float*)d_in[17];
    float* out = (float*)d_out;

    void* pa = nullptr; cudaGetSymbolAddress(&pa, g_arena);
    void* pi = nullptr; cudaGetSymbolAddress(&pi, g_iarena);
    float* F = (float*)pa;
    int* toks = (int*)pi;
    int* counts = toks + NEXP * T_TOK;

    float* x     = F + OFF_X;
    float* qkv   = F + OFF_QKV;
    float* attn  = F + OFF_ATTN;
    float* h     = F + OFF_H;
    float* y     = F + OFF_Y;
    float* moe   = F + OFF_MOE;
    float* sint  = F + OFF_SINT;
    float* logit = F + OFF_LOG;
    float* g     = F + OFF_G;
    float* wts   = F + OFF_WTS;
    float* inter = F + OFF_INT;

    zero_counts_kernel<<<1, 64>>>(counts);

    // attention block
    rmsnorm_kernel<<<T_TOK, 256>>>(hid, ln1, x);
    gemm_nt_kernel<<<dim3(16, 16), 256>>>(x, HDIM, q_w, HDIM, q_b, nullptr, 0, nullptr,
                                          qkv + 0, 1536, T_TOK, 1024, HDIM);
    gemm_nt_kernel<<<dim3(4, 16), 256>>>(x, HDIM, k_w, HDIM, k_b, nullptr, 0, nullptr,
                                         qkv + 1024, 1536, T_TOK, 256, HDIM);
    gemm_nt_kernel<<<dim3(4, 16), 256>>>(x, HDIM, v_w, HDIM, v_b, nullptr, 0, nullptr,
                                         qkv + 1280, 1536, T_TOK, 256, HDIM);
    rope_kernel<<<T_TOK, 256>>>(qkv);
    attn_kernel<<<dim3(SSEQ / 32, NHQ, BB), 256>>>(qkv, attn);
    gemm_nt_kernel<<<dim3(16, 16), 256>>>(attn, HDIM, o_w, HDIM, nullptr, hid, HDIM, nullptr,
                                          h, HDIM, T_TOK, HDIM, HDIM);

    // MoE block
    rmsnorm_kernel<<<T_TOK, 256>>>(h, ln2, y);
    gemm_nt_kernel<<<dim3(1, 16), 256>>>(y, HDIM, gate_w, HDIM, nullptr, nullptr, 0, nullptr,
                                         logit, NEXP, T_TOK, NEXP, HDIM);
    router_kernel<<<T_TOK / 256, 256>>>(logit, counts, toks, wts);

    // shared expert -> moe (writes all of moe)
    gemm_nt_gateup_kernel<<<dim3(IS / 64, T_TOK / 64), 256>>>(y, HDIM, s_gate, s_up, HDIM,
                                                              sint, IS, T_TOK, IS, HDIM);
    sgate_kernel<<<T_TOK, 256>>>(y, shg, g);
    gemm_nt_kernel<<<dim3(16, 16), 256>>>(sint, IS, s_down, IS, nullptr, nullptr, 0, g,
                                          moe, HDIM, T_TOK, HDIM, IS);

    // routed experts -> atomic add into moe
    expert_gateup_kernel<<<dim3(IE / 64, T_TOK / 64, NEXP), 256>>>(y, w_gate, w_up,
                                                                   toks, counts, inter);
    expert_down_kernel<<<dim3(HDIM / 64, T_TOK / 128, NEXP), 256>>>(inter, w_down,
                                                                    toks, counts, wts, moe);

    // final residual
    add_kernel<<<2048, 256>>>(h, moe, out, T_TOK * HDIM);
}

// round 5
// speedup vs baseline: 1.5650x; 1.5650x over previous
#include <cuda_runtime.h>
#include <math.h>
#include <stdint.h>

// ---------------- problem constants ----------------
#define T_TOK 2048      // B*S
#define HDIM  1024
#define SSEQ  1024
#define BB    2
#define NHQ   16
#define NKVH  4
#define NEXP  64
#define TOPK  8
#define IE    512
#define IS    1408

// ---------------- scratch arena (static, no allocs) ----------------
static const size_t OFF_X    = 0;          // [T,1024]
static const size_t OFF_QKV  = 2097152;    // [T,1536]  q|k|v packed
static const size_t OFF_ATTN = 5242880;    // [T,1024]
static const size_t OFF_H    = 7340032;    // [T,1024]
static const size_t OFF_Y    = 9437184;    // [T,1024]
static const size_t OFF_MOE  = 11534336;   // [T,1024]
static const size_t OFF_SINT = 13631488;   // [T,1408]
static const size_t OFF_LOG  = 16515072;   // [T,64]
static const size_t OFF_G    = 16646144;   // [T]
static const size_t OFF_WTS  = 16648192;   // [E,2048]
static const size_t OFF_INT  = 16779264;   // [E,2048,512]
__device__ float g_arena[83888128];
__device__ int   g_iarena[131136];         // toks [E,2048] then counts[64]

// ---------------- helpers ----------------
__device__ __forceinline__ float block_sum_256(float v) {
    __shared__ float red[8];
    #pragma unroll
    for (int o = 16; o; o >>= 1) v += __shfl_xor_sync(0xffffffffu, v, o);
    if ((threadIdx.x & 31) == 0) red[threadIdx.x >> 5] = v;
    __syncthreads();
    if (threadIdx.x == 0) {
        float s = 0.f;
        #pragma unroll
        for (int i = 0; i < 8; i++) s += red[i];
        red[0] = s;
    }
    __syncthreads();
    return red[0];
}

__device__ __forceinline__ uint32_t f2tf32(float f) {
    uint32_t u;
    asm("cvt.rna.tf32.f32 %0, %1;" : "=r"(u) : "f"(f));
    return u;
}

#define MMA_TF32(d, a, b)                                                      \
    asm volatile("mma.sync.aligned.m16n8k8.row.col.f32.tf32.tf32.f32 "         \
                 "{%0,%1,%2,%3}, {%4,%5,%6,%7}, {%8,%9}, {%0,%1,%2,%3};"       \
                 : "+f"(d[0]), "+f"(d[1]), "+f"(d[2]), "+f"(d[3])              \
                 : "r"(a[0]), "r"(a[1]), "r"(a[2]), "r"(a[3]),                 \
                   "r"(b[0]), "r"(b[1]))

// ---------------- elementwise / norm kernels ----------------
__global__ void zero_counts_kernel(int* counts) { counts[threadIdx.x] = 0; }

__global__ void rmsnorm_kernel(const float* __restrict__ x, const float* __restrict__ w,
                               float* __restrict__ out) {
    int t = blockIdx.x;
    const float* xr = x + (size_t)t * HDIM;
    float s = 0.f;
    for (int i = threadIdx.x; i < HDIM; i += 256) { float v = xr[i]; s += v * v; }
    s = block_sum_256(s);
    float inv = rsqrtf(s * (1.0f / HDIM) + 1e-6f);
    float* orow = out + (size_t)t * HDIM;
    for (int i = threadIdx.x; i < HDIM; i += 256) orow[i] = xr[i] * inv * w[i];
}

__global__ void sgate_kernel(const float* __restrict__ y, const float* __restrict__ shw,
                             float* __restrict__ g) {
    int t = blockIdx.x;
    const float* yr = y + (size_t)t * HDIM;
    float s = 0.f;
    for (int i = threadIdx.x; i < HDIM; i += 256) s += yr[i] * shw[i];
    s = block_sum_256(s);
    if (threadIdx.x == 0) g[t] = 1.0f / (1.0f + expf(-s));
}

__global__ void rope_kernel(float* __restrict__ qkv) {
    __shared__ float cs[32], sn[32];
    int t = blockIdx.x;
    int s = t & (SSEQ - 1);
    if (threadIdx.x < 32) {
        double inv = exp(-(double)threadIdx.x / 32.0 * log(1000000.0));
        double ang = (double)s * inv;
        cs[threadIdx.x] = (float)cos(ang);
        sn[threadIdx.x] = (float)sin(ang);
    }
    __syncthreads();
    float* base = qkv + (size_t)t * 1536;
    for (int w = threadIdx.x; w < 20 * 32; w += blockDim.x) {
        int hh = w >> 5, i = w & 31;
        float* p = base + (hh < 16 ? hh * 64 : 1024 + (hh - 16) * 64);
        float x1 = p[i], x2 = p[i + 32];
        float c = cs[i], s2 = sn[i];
        p[i]      = x1 * c - x2 * s2;
        p[i + 32] = x2 * c + x1 * s2;
    }
}

__global__ void add_kernel(const float* __restrict__ a, const float* __restrict__ b,
                           float* __restrict__ o, int n) {
    for (int i = blockIdx.x * blockDim.x + threadIdx.x; i < n; i += gridDim.x * blockDim.x)
        o[i] = a[i] + b[i];
}

// ---------------- SIMT NT GEMM (router logits only, N=64) ----------------
__global__ void __launch_bounds__(256) gemm_nt_kernel(
    const float* __restrict__ A, int lda,
    const float* __restrict__ B, int ldb,
    float* __restrict__ C, int ldc,
    int M, int N, int K)
{
    __shared__ float As[16][128];
    __shared__ float Bs[16][64];
    const int mb = blockIdx.y * 128;
    const int nb = blockIdx.x * 64;
    const int tid = threadIdx.x;
    const int tm = (tid >> 4) * 8;
    const int tn = (tid & 15) * 4;
    float acc[8][4];
    #pragma unroll
    for (int i = 0; i < 8; i++)
        #pragma unroll
        for (int j = 0; j < 4; j++) acc[i][j] = 0.f;

    for (int kb = 0; kb < K; kb += 16) {
        #pragma unroll
        for (int i = 0; i < 2; i++) {
            int f4 = tid + i * 256;
            int m = f4 >> 2, k4 = (f4 & 3) << 2;
            float4 v = make_float4(0.f, 0.f, 0.f, 0.f);
            int gm = mb + m;
            if (gm < M) v = *(const float4*)(A + (size_t)gm * lda + kb + k4);
            As[k4][m] = v.x; As[k4 + 1][m] = v.y; As[k4 + 2][m] = v.z; As[k4 + 3][m] = v.w;
        }
        {
            int n = tid >> 2, k4 = (tid & 3) << 2;
            int gn = nb + n;
            float4 v = make_float4(0.f, 0.f, 0.f, 0.f);
            if (gn < N) v = *(const float4*)(B + (size_t)gn * ldb + kb + k4);
            Bs[k4][n] = v.x; Bs[k4 + 1][n] = v.y; Bs[k4 + 2][n] = v.z; Bs[k4 + 3][n] = v.w;
        }
        __syncthreads();
        #pragma unroll
        for (int k = 0; k < 16; k++) {
            float4 a0 = *(const float4*)&As[k][tm];
            float4 a1 = *(const float4*)&As[k][tm + 4];
            float4 b  = *(const float4*)&Bs[k][tn];
            float av[8] = {a0.x, a0.y, a0.z, a0.w, a1.x, a1.y, a1.z, a1.w};
            float bv[4] = {b.x, b.y, b.z, b.w};
            #pragma unroll
            for (int i = 0; i < 8; i++)
                #pragma unroll
                for (int j = 0; j < 4; j++) acc[i][j] += av[i] * bv[j];
        }
        __syncthreads();
    }
    #pragma unroll
    for (int i = 0; i < 8; i++) {
        int gm = mb + tm + i;
        if (gm >= M) break;
        #pragma unroll
        for (int j = 0; j < 4; j++) {
            int gn = nb + tn + j;
            if (gn < N) C[(size_t)gm * ldc + gn] = acc[i][j];
        }
    }
}

// ---------------- tf32 tensor-core GEMM, 128x128x32 blocks ----------------
// BNT: 0 = B is [K,N] n-contiguous (NN), 1 = B is [N,K] k-contiguous (NT)
// AMODE: 0 = plain A rows, 1 = gather via toks, 2 = expert slot rows (A += e*strideAe)
// EPI: 0 = C = res + scale*(acc+bias); 1 = C = silu(C)*acc; 2 = atomicAdd(moe, w*acc)
template<int BNT, int AMODE, int EPI>
__global__ void __launch_bounds__(256) mma_kernel(
    const float* __restrict__ A, int lda, size_t strideAe,
    const float* __restrict__ B, int ldb, size_t strideBe,
    const float* __restrict__ bias,
    const float* __restrict__ res, int ldres,
    const float* __restrict__ scale,
    const int* __restrict__ toks, const int* __restrict__ counts,
    const float* __restrict__ wts,
    float* __restrict__ C, int ldc, size_t strideCe,
    int M, int N, int K)
{
    const int e = blockIdx.z;
    int bound = M;
    if (AMODE != 0) bound = counts[e];
    const int mb = blockIdx.y * 128;
    if (mb >= bound) return;
    const int nb = blockIdx.x * 128;
    if (AMODE == 2) A += (size_t)e * strideAe;
    B += (size_t)e * strideBe;
    C += (size_t)e * strideCe;

    __shared__ uint32_t As[128][36];   // [m][k] pad 36 (conflict-free frag reads)
    __shared__ uint32_t Bs[32][136];   // [k][n] pad 136 (conflict-free frag reads)

    const int tid = threadIdx.x;
    const int wid = tid >> 5, lane = tid & 31;
    const int g = lane >> 2, tg = lane & 3;
    const int wm = (wid & 1) * 64, wn = (wid >> 1) * 32;

    // ---- global load descriptors ----
    const float* aptr[4]; bool aval[4]; int a_m[4], a_k[4];
    #pragma unroll
    for (int i = 0; i < 4; i++) {
        int id = tid + i * 256;
        int m = id >> 3, k4 = (id & 7) << 2;
        int gm = mb + m;
        aval[i] = gm < bound;
        int row = aval[i] ? gm : 0;
        if (AMODE == 1) row = aval[i] ? toks[e * T_TOK + gm] : 0;
        aptr[i] = A + (size_t)row * lda + k4;
        a_m[i] = m; a_k[i] = k4;
    }
    const float* bptr[4]; int b_k[4], b_n[4];
    #pragma unroll
    for (int i = 0; i < 4; i++) {
        int id = tid + i * 256;
        if (BNT == 0) {
            int kk = id >> 5, n4 = (id & 31) << 2;
            bptr[i] = B + (size_t)kk * ldb + nb + n4;
            b_k[i] = kk; b_n[i] = n4;
        } else {
            int kq = id >> 7, n = id & 127;
            bptr[i] = B + (size_t)(nb + n) * ldb + kq * 4;
            b_k[i] = kq * 4; b_n[i] = n;
        }
    }

    float acc[4][4][4];
    #pragma unroll
    for (int mt = 0; mt < 4; mt++)
        #pragma unroll
        for (int nt = 0; nt < 4; nt++)
            #pragma unroll
            for (int q = 0; q < 4; q++) acc[mt][nt][q] = 0.f;

    float4 ra[4], rb[4];

    // prologue load
    #pragma unroll
    for (int i = 0; i < 4; i++)
        ra[i] = aval[i] ? *(const float4*)(aptr[i]) : make_float4(0.f, 0.f, 0.f, 0.f);
    #pragma unroll
    for (int i = 0; i < 4; i++)
        rb[i] = *(const float4*)(bptr[i]);

    for (int kb = 0; kb < K; kb += 32) {
        // store current regs -> smem (with round-to-nearest tf32)
        #pragma unroll
        for (int i = 0; i < 4; i++) {
            uint32_t* p = &As[a_m[i]][a_k[i]];
            p[0] = f2tf32(ra[i].x); p[1] = f2tf32(ra[i].y);
            p[2] = f2tf32(ra[i].z); p[3] = f2tf32(ra[i].w);
        }
        #pragma unroll
        for (int i = 0; i < 4; i++) {
            if (BNT == 0) {
                uint32_t* p = &Bs[b_k[i]][b_n[i]];
                p[0] = f2tf32(rb[i].x); p[1] = f2tf32(rb[i].y);
                p[2] = f2tf32(rb[i].z); p[3] = f2tf32(rb[i].w);
            } else {
                Bs[b_k[i] + 0][b_n[i]] = f2tf32(rb[i].x);
                Bs[b_k[i] + 1][b_n[i]] = f2tf32(rb[i].y);
                Bs[b_k[i] + 2][b_n[i]] = f2tf32(rb[i].z);
                Bs[b_k[i] + 3][b_n[i]] = f2tf32(rb[i].w);
            }
        }
        __syncthreads();

        // prefetch next chunk while computing
        bool more = (kb + 32) < K;
        if (more) {
            int kn = kb + 32;
            #pragma unroll
            for (int i = 0; i < 4; i++)
                ra[i] = aval[i] ? *(const float4*)(aptr[i] + kn)
                                : make_float4(0.f, 0.f, 0.f, 0.f);
            #pragma unroll
            for (int i = 0; i < 4; i++) {
                if (BNT == 0) rb[i] = *(const float4*)(bptr[i] + (size_t)kn * ldb);
                else          rb[i] = *(const float4*)(bptr[i] + kn);
            }
        }

        // compute 4 k-steps of 8
        #pragma unroll
        for (int ks = 0; ks < 32; ks += 8) {
            uint32_t af[4][4], bf[4][2];
            #pragma unroll
            for (int mt = 0; mt < 4; mt++) {
                int r = wm + mt * 16 + g;
                af[mt][0] = As[r][ks + tg];
                af[mt][1] = As[r + 8][ks + tg];
                af[mt][2] = As[r][ks + tg + 4];
                af[mt][3] = As[r + 8][ks + tg + 4];
            }
            #pragma unroll
            for (int nt = 0; nt < 4; nt++) {
                int c = wn + nt * 8 + g;
                bf[nt][0] = Bs[ks + tg][c];
                bf[nt][1] = Bs[ks + tg + 4][c];
            }
            #pragma unroll
            for (int mt = 0; mt < 4; mt++)
                #pragma unroll
                for (int nt = 0; nt < 4; nt++)
                    MMA_TF32(acc[mt][nt], af[mt], bf[nt]);
        }
        __syncthreads();
    }

    // ---- epilogue ----
    #pragma unroll
    for (int mt = 0; mt < 4; mt++) {
        int rbase = mb + wm + mt * 16 + g;
        #pragma unroll
        for (int half = 0; half < 2; half++) {
            int rr = rbase + half * 8;
            if (rr >= bound) continue;
            if (EPI == 2) {
                int t = toks[e * T_TOK + rr];
                float w = wts[e * T_TOK + rr];
                float* mp = C + (size_t)t * ldc;
                #pragma unroll
                for (int nt = 0; nt < 4; nt++) {
                    int c = nb + wn + nt * 8 + 2 * tg;
                    atomicAdd(&mp[c],     w * acc[mt][nt][half * 2 + 0]);
                    atomicAdd(&mp[c + 1], w * acc[mt][nt][half * 2 + 1]);
                }
            } else if (EPI == 1) {
                float* cp = C + (size_t)rr * ldc;
                #pragma unroll
                for (int nt = 0; nt < 4; nt++) {
                    int c = nb + wn + nt * 8 + 2 * tg;
                    float2 p = *(float2*)&cp[c];
                    float v0 = p.x / (1.0f + expf(-p.x)) * acc[mt][nt][half * 2 + 0];
                    float v1 = p.y / (1.0f + expf(-p.y)) * acc[mt][nt][half * 2 + 1];
                    *(float2*)&cp[c] = make_float2(v0, v1);
                }
            } else {
                float sc = scale ? scale[rr] : 1.f;
                float* cp = C + (size_t)rr * ldc;
                const float* rp = res ? res + (size_t)rr * ldres : nullptr;
                #pragma unroll
                for (int nt = 0; nt < 4; nt++) {
                    int c = nb + wn + nt * 8 + 2 * tg;
                    float v0 = acc[mt][nt][half * 2 + 0];
                    float v1 = acc[mt][nt][half * 2 + 1];
                    if (bias) { v0 += bias[c]; v1 += bias[c + 1]; }
                    v0 *= sc; v1 *= sc;
                    if (rp) { v0 += rp[c]; v1 += rp[c + 1]; }
                    *(float2*)&cp[c] = make_float2(v0, v1);
                }
            }
        }
    }
}

// ---------------- router top-k ----------------
__global__ void router_kernel(const float* __restrict__ logits, int* __restrict__ counts,
                              int* __restrict__ toks, float* __restrict__ wts) {
    int t = blockIdx.x * blockDim.x + threadIdx.x;
    if (t >= T_TOK) return;
    float v[NEXP];
    float mx = -1e30f;
    for (int e = 0; e < NEXP; e++) { v[e] = logits[t * NEXP + e]; mx = fmaxf(mx, v[e]); }
    for (int e = 0; e < NEXP; e++) v[e] = expf(v[e] - mx);
    int idx[TOPK]; float w8[TOPK]; float tw = 0.f;
    for (int j = 0; j < TOPK; j++) {
        int am = 0; float bm = -1.f;
        for (int e = 0; e < NEXP; e++) if (v[e] > bm) { bm = v[e]; am = e; }
        idx[j] = am; w8[j] = bm; tw += bm; v[am] = -2.f;
    }
    for (int j = 0; j < TOPK; j++) {
        int e = idx[j];
        int p = atomicAdd(&counts[e], 1);
        toks[e * T_TOK + p] = t;
        wts[e * T_TOK + p] = w8[j] / tw;
    }
}

// ---------------- flash attention (causal, GQA 16q/4kv, HD=64) ----------------
__global__ void __launch_bounds__(256) attn_kernel(const float* __restrict__ qkv,
                                                   float* __restrict__ out) {
    const int qt = blockIdx.x, h = blockIdx.y, b = blockIdx.z;
    const int q0 = qt * 32;
    const int kvh = h >> 2;
    __shared__ float Qs[32][68];
    __shared__ float KVs[64][68];
    __shared__ float Ss[32][68];
    const int tid = threadIdx.x;
    const int r = tid >> 3;
    const int cth = tid & 7;
    for (int i = tid; i < 32 * 64; i += 256) {
        int rr = i >> 6, d = i & 63;
        Qs[rr][d] = qkv[(size_t)(b * SSEQ + q0 + rr) * 1536 + h * 64 + d];
    }
    float m = -1e30f, l = 0.f;
    float oa[8];
    #pragma unroll
    for (int i = 0; i < 8; i++) oa[i] = 0.f;
    const int qg = q0 + r;
    const int ntiles = q0 / 64 + 1;
    for (int tkv = 0; tkv < ntiles; tkv++) {
        const int kb = tkv * 64;
        for (int i = tid; i < 64 * 64; i += 256) {
            int rr = i >> 6, d = i & 63;
            KVs[rr][d] = qkv[(size_t)(b * SSEQ + kb + rr) * 1536 + 1024 + kvh * 64 + d];
        }
        __syncthreads();
        float sv[8];
        #pragma unroll
        for (int ci = 0; ci < 8; ci++) {
            int c = cth + ci * 8;
            float s = 0.f;
            #pragma unroll
            for (int d = 0; d < 64; d++) s += Qs[r][d] * KVs[c][d];
            sv[ci] = (kb + c <= qg) ? s * 0.125f : -1e30f;
        }
        float tmax = sv[0];
        #pragma unroll
        for (int ci = 1; ci < 8; ci++) tmax = fmaxf(tmax, sv[ci]);
        #pragma unroll
        for (int o = 4; o; o >>= 1) tmax = fmaxf(tmax, __shfl_xor_sync(0xffffffffu, tmax, o, 8));
        float newm = fmaxf(m, tmax);
        float corr = expf(m - newm);
        float ls = 0.f;
        #pragma unroll
        for (int ci = 0; ci < 8; ci++) {
            float p = expf(sv[ci] - newm);
            Ss[r][cth + ci * 8] = p;
            ls += p;
        }
        #pragma unroll
        for (int o = 4; o; o >>= 1) ls += __shfl_xor_sync(0xffffffffu, ls, o, 8);
        l = l * corr + ls;
        #pragma unroll
        for (int i = 0; i < 8; i++) oa[i] *= corr;
        m = newm;
        __syncthreads();
        for (int i = tid; i < 64 * 64; i += 256) {
            int rr = i >> 6, d = i & 63;
            KVs[rr][d] = qkv[(size_t)(b * SSEQ + kb + rr) * 1536 + 1280 + kvh * 64 + d];
        }
        __syncthreads();
        #pragma unroll 16
        for (int k = 0; k < 64; k++) {
            float p = Ss[r][k];
            #pragma unroll
            for (int i = 0; i < 8; i++) oa[i] += p * KVs[k][cth + i * 8];
        }
        __syncthreads();
    }
    float inv = 1.f / l;
    #pragma unroll
    for (int i = 0; i < 8; i++)
        out[(size_t)(b * SSEQ + q0 + r) * 1024 + h * 64 + cth + i * 8] = oa[i] * inv;
}

// ---------------- launch ----------------
extern "C" void kernel_launch(void* const* d_in, const int* in_sizes, int n_in,
                              void* d_out, int out_size) {
    const float* hid    = (const float*)d_in[0];
    const float* ln1    = (const float*)d_in[1];
    const float* ln2    = (const float*)d_in[2];
    const float* q_w    = (const float*)d_in[3];
    const float* q_b    = (const float*)d_in[4];
    const float* k_w    = (const float*)d_in[5];
    const float* k_b    = (const float*)d_in[6];
    const float* v_w    = (const float*)d_in[7];
    const float* v_b    = (const float*)d_in[8];
    const float* o_w    = (const float*)d_in[9];
    const float* gate_w = (const float*)d_in[10];
    const float* w_gate = (const float*)d_in[11];
    const float* w_up   = (const float*)d_in[12];
    const float* w_down = (const float*)d_in[13];
    const float* s_gate = (const float*)d_in[14];
    const float* s_up   = (const float*)d_in[15];
    const float* s_down = (const float*)d_in[16];
    const float* shg    = (const float*)d_in[17];
    float* out = (float*)d_out;

    void* pa = nullptr; cudaGetSymbolAddress(&pa, g_arena);
    void* pi = nullptr; cudaGetSymbolAddress(&pi, g_iarena);
    float* F = (float*)pa;
    int* toks = (int*)pi;
    int* counts = toks + NEXP * T_TOK;

    float* x     = F + OFF_X;
    float* qkv   = F + OFF_QKV;
    float* attn  = F + OFF_ATTN;
    float* h     = F + OFF_H;
    float* y     = F + OFF_Y;
    float* moe   = F + OFF_MOE;
    float* sint  = F + OFF_SINT;
    float* logit = F + OFF_LOG;
    float* g     = F + OFF_G;
    float* wts   = F + OFF_WTS;
    float* inter = F + OFF_INT;

    zero_counts_kernel<<<1, 64>>>(counts);

    // ---- attention block ----
    rmsnorm_kernel<<<T_TOK, 256>>>(hid, ln1, x);
    // q
    mma_kernel<1, 0, 0><<<dim3(8, 16, 1), 256>>>(
        x, HDIM, 0, q_w, HDIM, 0, q_b, nullptr, 0, nullptr,
        nullptr, nullptr, nullptr, qkv, 1536, 0, T_TOK, 1024, HDIM);
    // k
    mma_kernel<1, 0, 0><<<dim3(2, 16, 1), 256>>>(
        x, HDIM, 0, k_w, HDIM, 0, k_b, nullptr, 0, nullptr,
        nullptr, nullptr, nullptr, qkv + 1024, 1536, 0, T_TOK, 256, HDIM);
    // v
    mma_kernel<1, 0, 0><<<dim3(2, 16, 1), 256>>>(
        x, HDIM, 0, v_w, HDIM, 0, v_b, nullptr, 0, nullptr,
        nullptr, nullptr, nullptr, qkv + 1280, 1536, 0, T_TOK, 256, HDIM);
    rope_kernel<<<T_TOK, 256>>>(qkv);
    attn_kernel<<<dim3(SSEQ / 32, NHQ, BB), 256>>>(qkv, attn);
    // o-proj + residual
    mma_kernel<1, 0, 0><<<dim3(8, 16, 1), 256>>>(
        attn, HDIM, 0, o_w, HDIM, 0, nullptr, hid, HDIM, nullptr,
        nullptr, nullptr, nullptr, h, HDIM, 0, T_TOK, 1024, HDIM);

    // ---- MoE block ----
    rmsnorm_kernel<<<T_TOK, 256>>>(h, ln2, y);
    gemm_nt_kernel<<<dim3(1, 16), 256>>>(y, HDIM, gate_w, HDIM, logit, NEXP,
                                         T_TOK, NEXP, HDIM);
    router_kernel<<<T_TOK / 256, 256>>>(logit, counts, toks, wts);

    // shared expert: gate -> sint, up fused silu*mul -> sint
    mma_kernel<1, 0, 0><<<dim3(11, 16, 1), 256>>>(
        y, HDIM, 0, s_gate, HDIM, 0, nullptr, nullptr, 0, nullptr,
        nullptr, nullptr, nullptr, sint, IS, 0, T_TOK, IS, HDIM);
    mma_kernel<1, 0, 1><<<dim3(11, 16, 1), 256>>>(
        y, HDIM, 0, s_up, HDIM, 0, nullptr, nullptr, 0, nullptr,
        nullptr, nullptr, nullptr, sint, IS, 0, T_TOK, IS, HDIM);
    sgate_kernel<<<T_TOK, 256>>>(y, shg, g);
    // shared down * sigmoid-gate -> moe (writes all of moe)
    mma_kernel<1, 0, 0><<<dim3(8, 16, 1), 256>>>(
        sint, IS, 0, s_down, IS, 0, nullptr, nullptr, 0, g,
        nullptr, nullptr, nullptr, moe, HDIM, 0, T_TOK, 1024, IS);

    // routed experts: gate -> inter, up fused silu*mul -> inter, down scatter -> moe
    mma_kernel<0, 1, 0><<<dim3(4, 16, NEXP), 256>>>(
        y, HDIM, 0, w_gate, IE, (size_t)HDIM * IE, nullptr, nullptr, 0, nullptr,
        toks, counts, nullptr, inter, IE, (size_t)T_TOK * IE, T_TOK, IE, HDIM);
    mma_kernel<0, 1, 1><<<dim3(4, 16, NEXP), 256>>>(
        y, HDIM, 0, w_up, IE, (size_t)HDIM * IE, nullptr, nullptr, 0, nullptr,
        toks, counts, nullptr, inter, IE, (size_t)T_TOK * IE, T_TOK, IE, HDIM);
    mma_kernel<0, 2, 2><<<dim3(8, 16, NEXP), 256>>>(
        inter, IE, (size_t)T_TOK * IE, w_down, HDIM, (size_t)IE * HDIM,
        nullptr, nullptr, 0, nullptr,
        toks, counts, wts, moe, HDIM, 0, T_TOK, 1024, IE);

    // final residual
    add_kernel<<<2048, 256>>>(h, moe, out, T_TOK * HDIM);
}

// round 8
// speedup vs baseline: 1.9952x; 1.2748x over previous
#include <cuda_runtime.h>
#include <math.h>
#include <stdint.h>

// ---------------- problem constants ----------------
#define T_TOK 2048      // B*S
#define HDIM  1024
#define SSEQ  1024
#define BB    2
#define NHQ   16
#define NKVH  4
#define NEXP  64
#define TOPK  8
#define IE    512
#define IS    1408

// ---------------- scratch arena (static, no allocs) ----------------
static const size_t OFF_X    = 0;          // [T,1024]
static const size_t OFF_QKV  = 2097152;    // [T,1536]  q|k|v packed
static const size_t OFF_ATTN = 5242880;    // [T,1024]
static const size_t OFF_H    = 7340032;    // [T,1024]
static const size_t OFF_Y    = 9437184;    // [T,1024]
static const size_t OFF_MOE  = 11534336;   // [T,1024]
static const size_t OFF_SINT = 13631488;   // [T,1408]
static const size_t OFF_LOG  = 16515072;   // [T,64]
static const size_t OFF_G    = 16646144;   // [T]
static const size_t OFF_WTS  = 16648192;   // [E,2048]
static const size_t OFF_INT  = 16779264;   // [E,2048,512]
__device__ float g_arena[83888128];
__device__ int   g_iarena[131136];         // toks [E,2048] then counts[64]

// ---------------- helpers ----------------
__device__ __forceinline__ float block_sum_256(float v) {
    __shared__ float red[8];
    #pragma unroll
    for (int o = 16; o; o >>= 1) v += __shfl_xor_sync(0xffffffffu, v, o);
    if ((threadIdx.x & 31) == 0) red[threadIdx.x >> 5] = v;
    __syncthreads();
    if (threadIdx.x == 0) {
        float s = 0.f;
        #pragma unroll
        for (int i = 0; i < 8; i++) s += red[i];
        red[0] = s;
    }
    __syncthreads();
    return red[0];
}

__device__ __forceinline__ uint32_t f2tf32(float f) {
    uint32_t u;
    asm("cvt.rna.tf32.f32 %0, %1;" : "=r"(u) : "f"(f));
    return u;
}
__device__ __forceinline__ float roundtf(float f) { return __uint_as_float(f2tf32(f)); }

#define MMA_TF32(d, a, b)                                                      \
    asm volatile("mma.sync.aligned.m16n8k8.row.col.f32.tf32.tf32.f32 "         \
                 "{%0,%1,%2,%3}, {%4,%5,%6,%7}, {%8,%9}, {%0,%1,%2,%3};"       \
                 : "+f"(d[0]), "+f"(d[1]), "+f"(d[2]), "+f"(d[3])              \
                 : "r"(a[0]), "r"(a[1]), "r"(a[2]), "r"(a[3]),                 \
                   "r"(b[0]), "r"(b[1]))

__device__ __forceinline__ void cpasync16(uint32_t dst, const float* src, int sz) {
    asm volatile("cp.async.cg.shared.global [%0], [%1], 16, %2;"
                 :: "r"(dst), "l"(src), "r"(sz));
}
#define CP_COMMIT() asm volatile("cp.async.commit_group;")
#define CP_WAIT0()  asm volatile("cp.async.wait_group 0;")

// ---------------- elementwise / norm kernels ----------------
__global__ void zero_counts_kernel(int* counts) { counts[threadIdx.x] = 0; }

__global__ void rmsnorm_kernel(const float* __restrict__ x, const float* __restrict__ w,
                               float* __restrict__ out) {
    int t = blockIdx.x;
    const float* xr = x + (size_t)t * HDIM;
    float s = 0.f;
    for (int i = threadIdx.x; i < HDIM; i += 256) { float v = xr[i]; s += v * v; }
    s = block_sum_256(s);
    float inv = rsqrtf(s * (1.0f / HDIM) + 1e-6f);
    float* orow = out + (size_t)t * HDIM;
    // pre-round to tf32 grid: this buffer feeds tensor-core GEMMs as A
    for (int i = threadIdx.x; i < HDIM; i += 256) orow[i] = roundtf(xr[i] * inv * w[i]);
}

__global__ void sgate_kernel(const float* __restrict__ y, const float* __restrict__ shw,
                             float* __restrict__ g) {
    int t = blockIdx.x;
    const float* yr = y + (size_t)t * HDIM;
    float s = 0.f;
    for (int i = threadIdx.x; i < HDIM; i += 256) s += yr[i] * shw[i];
    s = block_sum_256(s);
    if (threadIdx.x == 0) g[t] = 1.0f / (1.0f + expf(-s));
}

__global__ void rope_kernel(float* __restrict__ qkv) {
    __shared__ float cs[32], sn[32];
    int t = blockIdx.x;
    int s = t & (SSEQ - 1);
    if (threadIdx.x < 32) {
        double inv = exp(-(double)threadIdx.x / 32.0 * log(1000000.0));
        double ang = (double)s * inv;
        cs[threadIdx.x] = (float)cos(ang);
        sn[threadIdx.x] = (float)sin(ang);
    }
    __syncthreads();
    float* base = qkv + (size_t)t * 1536;
    for (int w = threadIdx.x; w < 20 * 32; w += blockDim.x) {
        int hh = w >> 5, i = w & 31;
        float* p = base + (hh < 16 ? hh * 64 : 1024 + (hh - 16) * 64);
        float x1 = p[i], x2 = p[i + 32];
        float c = cs[i], s2 = sn[i];
        p[i]      = x1 * c - x2 * s2;
        p[i + 32] = x2 * c + x1 * s2;
    }
}

__global__ void add_kernel(const float* __restrict__ a, const float* __restrict__ b,
                           float* __restrict__ o, int n) {
    for (int i = blockIdx.x * blockDim.x + threadIdx.x; i < n; i += gridDim.x * blockDim.x)
        o[i] = a[i] + b[i];
}

// ---------------- SIMT NT GEMM (router logits only, N=64) ----------------
__global__ void __launch_bounds__(256) gemm_nt_kernel(
    const float* __restrict__ A, int lda,
    const float* __restrict__ B, int ldb,
    float* __restrict__ C, int ldc,
    int M, int N, int K)
{
    __shared__ float As[16][128];
    __shared__ float Bs[16][64];
    const int mb = blockIdx.y * 128;
    const int nb = blockIdx.x * 64;
    const int tid = threadIdx.x;
    const int tm = (tid >> 4) * 8;
    const int tn = (tid & 15) * 4;
    float acc[8][4];
    #pragma unroll
    for (int i = 0; i < 8; i++)
        #pragma unroll
        for (int j = 0; j < 4; j++) acc[i][j] = 0.f;

    for (int kb = 0; kb < K; kb += 16) {
        #pragma unroll
        for (int i = 0; i < 2; i++) {
            int f4 = tid + i * 256;
            int m = f4 >> 2, k4 = (f4 & 3) << 2;
            float4 v = make_float4(0.f, 0.f, 0.f, 0.f);
            int gm = mb + m;
            if (gm < M) v = *(const float4*)(A + (size_t)gm * lda + kb + k4);
            As[k4][m] = v.x; As[k4 + 1][m] = v.y; As[k4 + 2][m] = v.z; As[k4 + 3][m] = v.w;
        }
        {
            int n = tid >> 2, k4 = (tid & 3) << 2;
            int gn = nb + n;
            float4 v = make_float4(0.f, 0.f, 0.f, 0.f);
            if (gn < N) v = *(const float4*)(B + (size_t)gn * ldb + kb + k4);
            Bs[k4][n] = v.x; Bs[k4 + 1][n] = v.y; Bs[k4 + 2][n] = v.z; Bs[k4 + 3][n] = v.w;
        }
        __syncthreads();
        #pragma unroll
        for (int k = 0; k < 16; k++) {
            float4 a0 = *(const float4*)&As[k][tm];
            float4 a1 = *(const float4*)&As[k][tm + 4];
            float4 b  = *(const float4*)&Bs[k][tn];
            float av[8] = {a0.x, a0.y, a0.z, a0.w, a1.x, a1.y, a1.z, a1.w};
            float bv[4] = {b.x, b.y, b.z, b.w};
            #pragma unroll
            for (int i = 0; i < 8; i++)
                #pragma unroll
                for (int j = 0; j < 4; j++) acc[i][j] += av[i] * bv[j];
        }
        __syncthreads();
    }
    #pragma unroll
    for (int i = 0; i < 8; i++) {
        int gm = mb + tm + i;
        if (gm >= M) break;
        #pragma unroll
        for (int j = 0; j < 4; j++) {
            int gn = nb + tn + j;
            if (gn < N) C[(size_t)gm * ldc + gn] = acc[i][j];
        }
    }
}

// ---------------- tf32 tensor-core GEMM, 128x128 block, cp.async 2-stage ----------------
// BN: 0 = B is [K,N] n-contiguous (NN), 1 = B is [N,K] k-contiguous (NT)
// AMODE: 0 = plain A rows, 1 = gather via toks, 2 = expert slot rows
// EPI: 0 = C = res + scale*(acc+bias); 1 = C = tf32(silu(C)*acc); 2 = atomicAdd(moe, w*acc)
// QKV: 1 = select B/bias by output-column range (q|k|v packed, N=1536)
// A must be pre-rounded to tf32; B is cvt.rna'd on fragment load.
#define KC     16
#define APAD   20      // row stride (words) for k-contiguous tiles
#define ASTAGE 2560    // 128*20 words per stage
#define BPADN  136     // row stride for NN [16][136]

template<int BN, int AMODE, int EPI, int QKV>
__global__ void __launch_bounds__(256) mma_kernel(
    const float* __restrict__ A, int lda, size_t strideAe,
    const float* __restrict__ B, int ldb, size_t strideBe,
    const float* __restrict__ B2, const float* __restrict__ B3,
    const float* __restrict__ bias, const float* __restrict__ bias2,
    const float* __restrict__ bias3,
    const float* __restrict__ res, int ldres,
    const float* __restrict__ scale,
    const int* __restrict__ toks, const int* __restrict__ counts,
    const float* __restrict__ wts,
    float* __restrict__ C, int ldc, size_t strideCe,
    int M, int N, int K)
{
    const int e = blockIdx.z;
    int bound = M;
    if (AMODE != 0) bound = counts[e];
    const int mb = blockIdx.y * 128;
    if (mb >= bound) return;
    const int nb = blockIdx.x * 128;
    if (AMODE == 2) A += (size_t)e * strideAe;
    B += (size_t)e * strideBe;
    C += (size_t)e * strideCe;

    // QKV column-range weight select
    const float* Bw = B;
    const float* bi = bias;
    int rowoff = 0;
    if (QKV) {
        if (nb >= 1280)      { Bw = B3; bi = bias3; rowoff = 1280; }
        else if (nb >= 1024) { Bw = B2; bi = bias2; rowoff = 1024; }
    }

    __shared__ float As[2][ASTAGE];
    __shared__ float Bs[2][ASTAGE];

    const int tid = threadIdx.x;
    const int wid = tid >> 5, lane = tid & 31;
    const int g = lane >> 2, tg = lane & 3;
    const int wm = (wid & 1) * 64, wn = (wid >> 1) * 32;

    const uint32_t smA = (uint32_t)__cvta_generic_to_shared(&As[0][0]);
    const uint32_t smB = (uint32_t)__cvta_generic_to_shared(&Bs[0][0]);

    // ---- per-thread cp.async descriptors: 2 A chunks + 2 B chunks ----
    const float* asrc[2]; int asz[2]; uint32_t adst[2];
    #pragma unroll
    for (int i = 0; i < 2; i++) {
        int id = tid + i * 256;           // 0..511
        int m = id >> 2, kq = id & 3;
        int gm = mb + m;
        bool valid = gm < bound;
        int row = valid ? gm : 0;
        if (AMODE == 1) row = valid ? toks[e * T_TOK + gm] : 0;
        asrc[i] = A + (size_t)row * lda + kq * 4;
        asz[i] = valid ? 16 : 0;
        adst[i] = smA + (uint32_t)(m * APAD + kq * 4) * 4u;
    }
    const float* bsrc[2]; uint32_t bdst[2];
    long bstep;                            // floats to advance per iteration
    #pragma unroll
    for (int i = 0; i < 2; i++) {
        int id = tid + i * 256;
        if (BN == 1) {
            int n = id >> 2, kq = id & 3;
            bsrc[i] = Bw + (size_t)(nb + n - rowoff) * ldb + kq * 4;
            bdst[i] = smB + (uint32_t)(n * APAD + kq * 4) * 4u;
        } else {
            int kk = id >> 5, n4 = (id & 31) << 2;
            bsrc[i] = B + (size_t)kk * ldb + nb + n4;
            bdst[i] = smB + (uint32_t)(kk * BPADN + n4) * 4u;
        }
    }
    bstep = (BN == 1) ? KC : (long)KC * ldb;

    float acc[4][4][4];
    #pragma unroll
    for (int mt = 0; mt < 4; mt++)
        #pragma unroll
        for (int nt = 0; nt < 4; nt++)
            #pragma unroll
            for (int q = 0; q < 4; q++) acc[mt][nt][q] = 0.f;

    const int niter = K / KC;

    // prologue: stage 0
    #pragma unroll
    for (int i = 0; i < 2; i++) cpasync16(adst[i], asrc[i], asz[i]);
    #pragma unroll
    for (int i = 0; i < 2; i++) cpasync16(bdst[i], bsrc[i], 16);
    CP_COMMIT();
    #pragma unroll
    for (int i = 0; i < 2; i++) { asrc[i] += KC; bsrc[i] += bstep; }

    for (int it = 0; it < niter; it++) {
        const int s = it & 1;
        CP_WAIT0();
        __syncthreads();
        if (it + 1 < niter) {
            const uint32_t soff = (uint32_t)((s ^ 1) * ASTAGE * 4);
            #pragma unroll
            for (int i = 0; i < 2; i++) cpasync16(adst[i] + soff, asrc[i], asz[i]);
            #pragma unroll
            for (int i = 0; i < 2; i++) cpasync16(bdst[i] + soff, bsrc[i], 16);
            CP_COMMIT();
            #pragma unroll
            for (int i = 0; i < 2; i++) { asrc[i] += KC; bsrc[i] += bstep; }
        }
        // compute 2 k-steps of 8
        #pragma unroll
        for (int ks = 0; ks < KC; ks += 8) {
            uint32_t af[4][4], bf[4][2];
            #pragma unroll
            for (int mt = 0; mt < 4; mt++) {
                int r = wm + mt * 16 + g;
                af[mt][0] = __float_as_uint(As[s][r * APAD + ks + tg]);
                af[mt][1] = __float_as_uint(As[s][(r + 8) * APAD + ks + tg]);
                af[mt][2] = __float_as_uint(As[s][r * APAD + ks + tg + 4]);
                af[mt][3] = __float_as_uint(As[s][(r + 8) * APAD + ks + tg + 4]);
            }
            #pragma unroll
            for (int nt = 0; nt < 4; nt++) {
                int c = wn + nt * 8 + g;
                if (BN == 1) {
                    bf[nt][0] = f2tf32(Bs[s][c * APAD + ks + tg]);
                    bf[nt][1] = f2tf32(Bs[s][c * APAD + ks + tg + 4]);
                } else {
                    bf[nt][0] = f2tf32(Bs[s][(ks + tg) * BPADN + c]);
                    bf[nt][1] = f2tf32(Bs[s][(ks + tg + 4) * BPADN + c]);
                }
            }
            #pragma unroll
            for (int mt = 0; mt < 4; mt++)
                #pragma unroll
                for (int nt = 0; nt < 4; nt++)
                    MMA_TF32(acc[mt][nt], af[mt], bf[nt]);
        }
        __syncthreads();
    }

    // ---- epilogue ----
    #pragma unroll
    for (int mt = 0; mt < 4; mt++) {
        int rbase = mb + wm + mt * 16 + g;
        #pragma unroll
        for (int half = 0; half < 2; half++) {
            int rr = rbase + half * 8;
            if (rr >= bound) continue;
            if (EPI == 2) {
                int t = toks[e * T_TOK + rr];
                float w = wts[e * T_TOK + rr];
                float* mp = C + (size_t)t * ldc;
                #pragma unroll
                for (int nt = 0; nt < 4; nt++) {
                    int c = nb + wn + nt * 8 + 2 * tg;
                    atomicAdd(&mp[c],     w * acc[mt][nt][half * 2 + 0]);
                    atomicAdd(&mp[c + 1], w * acc[mt][nt][half * 2 + 1]);
                }
            } else if (EPI == 1) {
                float* cp = C + (size_t)rr * ldc;
                #pragma unroll
                for (int nt = 0; nt < 4; nt++) {
                    int c = nb + wn + nt * 8 + 2 * tg;
                    float2 p = *(float2*)&cp[c];
                    float v0 = p.x / (1.0f + expf(-p.x)) * acc[mt][nt][half * 2 + 0];
                    float v1 = p.y / (1.0f + expf(-p.y)) * acc[mt][nt][half * 2 + 1];
                    *(float2*)&cp[c] = make_float2(roundtf(v0), roundtf(v1));
                }
            } else {
                float sc = scale ? scale[rr] : 1.f;
                float* cp = C + (size_t)rr * ldc;
                const float* rp = res ? res + (size_t)rr * ldres : nullptr;
                #pragma unroll
                for (int nt = 0; nt < 4; nt++) {
                    int c = nb + wn + nt * 8 + 2 * tg;
                    float v0 = acc[mt][nt][half * 2 + 0];
                    float v1 = acc[mt][nt][half * 2 + 1];
                    if (bi) { v0 += bi[c - rowoff]; v1 += bi[c + 1 - rowoff]; }
                    v0 *= sc; v1 *= sc;
                    if (rp) { v0 += rp[c]; v1 += rp[c + 1]; }
                    *(float2*)&cp[c] = make_float2(v0, v1);
                }
            }
        }
    }
}

// ---------------- router top-k ----------------
__global__ void router_kernel(const float* __restrict__ logits, int* __restrict__ counts,
                              int* __restrict__ toks, float* __restrict__ wts) {
    int t = blockIdx.x * blockDim.x + threadIdx.x;
    if (t >= T_TOK) return;
    float v[NEXP];
    float mx = -1e30f;
    for (int e = 0; e < NEXP; e++) { v[e] = logits[t * NEXP + e]; mx = fmaxf(mx, v[e]); }
    for (int e = 0; e < NEXP; e++) v[e] = expf(v[e] - mx);
    int idx[TOPK]; float w8[TOPK]; float tw = 0.f;
    for (int j = 0; j < TOPK; j++) {
        int am = 0; float bm = -1.f;
        for (int e = 0; e < NEXP; e++) if (v[e] > bm) { bm = v[e]; am = e; }
        idx[j] = am; w8[j] = bm; tw += bm; v[am] = -2.f;
    }
    for (int j = 0; j < TOPK; j++) {
        int e = idx[j];
        int p = atomicAdd(&counts[e], 1);
        toks[e * T_TOK + p] = t;
        wts[e * T_TOK + p] = w8[j] / tw;
    }
}

// ---------------- flash attention (causal, GQA 16q/4kv, HD=64) ----------------
__global__ void __launch_bounds__(256) attn_kernel(const float* __restrict__ qkv,
                                                   float* __restrict__ out) {
    const int qt = blockIdx.x, h = blockIdx.y, b = blockIdx.z;
    const int q0 = qt * 32;
    const int kvh = h >> 2;
    __shared__ float Qs[32][68];
    __shared__ float KVs[64][68];
    __shared__ float Ss[32][68];
    const int tid = threadIdx.x;
    const int r = tid >> 3;
    const int cth = tid & 7;
    for (int i = tid; i < 32 * 64; i += 256) {
        int rr = i >> 6, d = i & 63;
        Qs[rr][d] = qkv[(size_t)(b * SSEQ + q0 + rr) * 1536 + h * 64 + d];
    }
    float m = -1e30f, l = 0.f;
    float oa[8];
    #pragma unroll
    for (int i = 0; i < 8; i++) oa[i] = 0.f;
    const int qg = q0 + r;
    const int ntiles = q0 / 64 + 1;
    for (int tkv = 0; tkv < ntiles; tkv++) {
        const int kb = tkv * 64;
        for (int i = tid; i < 64 * 64; i += 256) {
            int rr = i >> 6, d = i & 63;
            KVs[rr][d] = qkv[(size_t)(b * SSEQ + kb + rr) * 1536 + 1024 + kvh * 64 + d];
        }
        __syncthreads();
        float sv[8];
        #pragma unroll
        for (int ci = 0; ci < 8; ci++) {
            int c = cth + ci * 8;
            float s = 0.f;
            #pragma unroll
            for (int d = 0; d < 64; d++) s += Qs[r][d] * KVs[c][d];
            sv[ci] = (kb + c <= qg) ? s * 0.125f : -1e30f;
        }
        float tmax = sv[0];
        #pragma unroll
        for (int ci = 1; ci < 8; ci++) tmax = fmaxf(tmax, sv[ci]);
        #pragma unroll
        for (int o = 4; o; o >>= 1) tmax = fmaxf(tmax, __shfl_xor_sync(0xffffffffu, tmax, o, 8));
        float newm = fmaxf(m, tmax);
        float corr = expf(m - newm);
        float ls = 0.f;
        #pragma unroll
        for (int ci = 0; ci < 8; ci++) {
            float p = expf(sv[ci] - newm);
            Ss[r][cth + ci * 8] = p;
            ls += p;
        }
        #pragma unroll
        for (int o = 4; o; o >>= 1) ls += __shfl_xor_sync(0xffffffffu, ls, o, 8);
        l = l * corr + ls;
        #pragma unroll
        for (int i = 0; i < 8; i++) oa[i] *= corr;
        m = newm;
        __syncthreads();
        for (int i = tid; i < 64 * 64; i += 256) {
            int rr = i >> 6, d = i & 63;
            KVs[rr][d] = qkv[(size_t)(b * SSEQ + kb + rr) * 1536 + 1280 + kvh * 64 + d];
        }
        __syncthreads();
        #pragma unroll 16
        for (int k = 0; k < 64; k++) {
            float p = Ss[r][k];
            #pragma unroll
            for (int i = 0; i < 8; i++) oa[i] += p * KVs[k][cth + i * 8];
        }
        __syncthreads();
    }
    float inv = 1.f / l;
    // pre-round: this buffer is A of the o-proj tensor-core GEMM
    #pragma unroll
    for (int i = 0; i < 8; i++)
        out[(size_t)(b * SSEQ + q0 + r) * 1024 + h * 64 + cth + i * 8] = roundtf(oa[i] * inv);
}

// ---------------- launch ----------------
extern "C" void kernel_launch(void* const* d_in, const int* in_sizes, int n_in,
                              void* d_out, int out_size) {
    const float* hid    = (const float*)d_in[0];
    const float* ln1    = (const float*)d_in[1];
    const float* ln2    = (const float*)d_in[2];
    const float* q_w    = (const float*)d_in[3];
    const float* q_b    = (const float*)d_in[4];
    const float* k_w    = (const float*)d_in[5];
    const float* k_b    = (const float*)d_in[6];
    const float* v_w    = (const float*)d_in[7];
    const float* v_b    = (const float*)d_in[8];
    const float* o_w    = (const float*)d_in[9];
    const float* gate_w = (const float*)d_in[10];
    const float* w_gate = (const float*)d_in[11];
    const float* w_up   = (const float*)d_in[12];
    const float* w_down = (const float*)d_in[13];
    const float* s_gate = (const float*)d_in[14];
    const float* s_up   = (const float*)d_in[15];
    const float* s_down = (const float*)d_in[16];
    const float* shg    = (const float*)d_in[17];
    float* out = (float*)d_out;

    void* pa = nullptr; cudaGetSymbolAddress(&pa, g_arena);
    void* pi = nullptr; cudaGetSymbolAddress(&pi, g_iarena);
    float* F = (float*)pa;
    int* toks = (int*)pi;
    int* counts = toks + NEXP * T_TOK;

    float* x     = F + OFF_X;
    float* qkv   = F + OFF_QKV;
    float* attn  = F + OFF_ATTN;
    float* h     = F + OFF_H;
    float* y     = F + OFF_Y;
    float* moe   = F + OFF_MOE;
    float* sint  = F + OFF_SINT;
    float* logit = F + OFF_LOG;
    float* g     = F + OFF_G;
    float* wts   = F + OFF_WTS;
    float* inter = F + OFF_INT;

    zero_counts_kernel<<<1, 64>>>(counts);

    // ---- attention block ----
    rmsnorm_kernel<<<T_TOK, 256>>>(hid, ln1, x);
    // fused QKV: N=1536 packed, per-column-range weight select
    mma_kernel<1, 0, 0, 1><<<dim3(12, 16, 1), 256>>>(
        x, HDIM, 0, q_w, HDIM, 0, k_w, v_w, q_b, k_b, v_b,
        nullptr, 0, nullptr, nullptr, nullptr, nullptr,
        qkv, 1536, 0, T_TOK, 1536, HDIM);
    rope_kernel<<<T_TOK, 256>>>(qkv);
    attn_kernel<<<dim3(SSEQ / 32, NHQ, BB), 256>>>(qkv, attn);
    // o-proj + residual
    mma_kernel<1, 0, 0, 0><<<dim3(8, 16, 1), 256>>>(
        attn, HDIM, 0, o_w, HDIM, 0, nullptr, nullptr, nullptr, nullptr, nullptr,
        hid, HDIM, nullptr, nullptr, nullptr, nullptr,
        h, HDIM, 0, T_TOK, 1024, HDIM);

    // ---- MoE block ----
    rmsnorm_kernel<<<T_TOK, 256>>>(h, ln2, y);
    gemm_nt_kernel<<<dim3(1, 16), 256>>>(y, HDIM, gate_w, HDIM, logit, NEXP,
                                         T_TOK, NEXP, HDIM);
    router_kernel<<<T_TOK / 256, 256>>>(logit, counts, toks, wts);

    // shared expert: gate -> sint, up fused silu*mul -> sint
    mma_kernel<1, 0, 0, 0><<<dim3(11, 16, 1), 256>>>(
        y, HDIM, 0, s_gate, HDIM, 0, nullptr, nullptr, nullptr, nullptr, nullptr,
        nullptr, 0, nullptr, nullptr, nullptr, nullptr,
        sint, IS, 0, T_TOK, IS, HDIM);
    mma_kernel<1, 0, 1, 0><<<dim3(11, 16, 1), 256>>>(
        y, HDIM, 0, s_up, HDIM, 0, nullptr, nullptr, nullptr, nullptr, nullptr,
        nullptr, 0, nullptr, nullptr, nullptr, nullptr,
        sint, IS, 0, T_TOK, IS, HDIM);
    sgate_kernel<<<T_TOK, 256>>>(y, shg, g);
    // shared down * sigmoid-gate -> moe (writes all of moe)
    mma_kernel<1, 0, 0, 0><<<dim3(8, 16, 1), 256>>>(
        sint, IS, 0, s_down, IS, 0, nullptr, nullptr, nullptr, nullptr, nullptr,
        nullptr, 0, g, nullptr, nullptr, nullptr,
        moe, HDIM, 0, T_TOK, 1024, IS);

    // routed experts: gate -> inter, up fused silu*mul -> inter, down scatter -> moe
    mma_kernel<0, 1, 0, 0><<<dim3(4, 16, NEXP), 256>>>(
        y, HDIM, 0, w_gate, IE, (size_t)HDIM * IE, nullptr, nullptr,
        nullptr, nullptr, nullptr, nullptr, 0, nullptr,
        toks, counts, nullptr, inter, IE, (size_t)T_TOK * IE, T_TOK, IE, HDIM);
    mma_kernel<0, 1, 1, 0><<<dim3(4, 16, NEXP), 256>>>(
        y, HDIM, 0, w_up, IE, (size_t)HDIM * IE, nullptr, nullptr,
        nullptr, nullptr, nullptr, nullptr, 0, nullptr,
        toks, counts, nullptr, inter, IE, (size_t)T_TOK * IE, T_TOK, IE, HDIM);
    mma_kernel<0, 2, 2, 0><<<dim3(8, 16, NEXP), 256>>>(
        inter, IE, (size_t)T_TOK * IE, w_down, HDIM, (size_t)IE * HDIM, nullptr, nullptr,
        nullptr, nullptr, nullptr, nullptr, 0, nullptr,
        toks, counts, wts, moe, HDIM, 0, T_TOK, 1024, IE);

    // final residual
    add_kernel<<<2048, 256>>>(h, moe, out, T_TOK * HDIM);
}